// round 5
// baseline (speedup 1.0000x reference)
#include <cuda_runtime.h>
#include <cuda_fp16.h>

// ---------------------------------------------------------------------------
// CharEmbeddingCNN: embed + 3x conv1d(k=3,4,5) + maxpool + relu + len-mask.
//
//   C_kj[c, o] = sum_i W_k[o, i, j] * emb[c, i]      (12 tables, 256x256, fp16)
//   y_k[n,o,t] = b_k[o] + sum_j C_kj[x[n,t+j], o]
//   out[n,o]   = mask(n) * relu(max_{k,t} y_k[n,o,t])
//
// R5: fused kernel, BALANCED build: 1536 jobs (16c x 32o x 256k) over
// 8 groups x 128 threads per CTA; every CTA executes 10-11 jobs. Grid
// barrier (sense-reversing, replay-safe), then the R3/R4 pool phases.
// ---------------------------------------------------------------------------

#define LSEQ  20
#define NTOT  8192            // 64 * 128
#define NPC   222             // n per CTA (37 groups)
#define NGRP  37
#define OTILES 4              // 4 tiles of 64 outputs
#define TBL_BYTES 32768       // per-table SMEM slice: 256 chars * 64 halves * 2B
#define CHSTRIDE 24           // shorts per n (20 used, padded for uint4)
#define SMEM_CHARS_OFF (5 * TBL_BYTES)
#define SMEM_TOTAL (SMEM_CHARS_OFF + NPC * CHSTRIDE * 2)
#define NCTA  148
#define NJOBS 1536            // 12 tables * 16 c-blocks(16) * 8 o-blocks(32)
#define NSLOTS 1184           // 148 CTAs * 8 groups
#define EXTRA  (NJOBS - NSLOTS)   // 352
#define GSCRATCH 6912         // bytes per group scratch (As 2304 + Bs 4352)

__device__ __align__(16) __half g_tbl_h[12 * 256 * 256];
__device__ unsigned g_count = 0;
__device__ volatile unsigned g_gen = 0;

// ---------------------------------------------------------------------------
// Build one 16c x 32o x 256k table tile with a 128-thread group.
// Thread tile 2c x 2o. Ascending-k fp32 accumulation (matches prior rounds).
// ---------------------------------------------------------------------------
__device__ __forceinline__ void build_job(
    int job, float* As, float* Bs,
    const float* __restrict__ emb,
    const float* __restrict__ w3, const float* __restrict__ w4,
    const float* __restrict__ w5,
    int tid_g, int bar_id)
{
    const int tbl = job >> 7;
    const int c0  = ((job >> 3) & 15) * 16;
    const int o0  = (job & 7) * 32;

    int k, j; const float* w;
    if (tbl < 3)      { k = 3; j = tbl;     w = w3; }
    else if (tbl < 7) { k = 4; j = tbl - 3; w = w4; }
    else              { k = 5; j = tbl - 7; w = w5; }
    const int wk = 256 * k;

    const int ty = tid_g >> 4;        // 0..7  -> c pair
    const int tx = tid_g & 15;        // 0..15 -> o pair

    float a00 = 0.f, a01 = 0.f, a10 = 0.f, a11 = 0.f;

    for (int chunk = 0; chunk < 8; chunk++) {
        const int kk = chunk * 32;
        asm volatile("bar.sync %0, 128;" :: "r"(bar_id));   // SMEM free
        #pragma unroll
        for (int r = 0; r < 4; r++) {                        // A: 16c x 32k
            int idx = tid_g + r * 128;
            int ci = idx >> 5, ki = idx & 31;
            As[ki * 18 + ci] = emb[(c0 + ci) * 256 + kk + ki];
        }
        #pragma unroll
        for (int r = 0; r < 8; r++) {                        // B: 32o x 32k
            int idx = tid_g + r * 128;
            int oi = idx >> 5, ki = idx & 31;
            Bs[ki * 34 + oi] = w[(o0 + oi) * wk + (kk + ki) * k + j];
        }
        asm volatile("bar.sync %0, 128;" :: "r"(bar_id));   // SMEM filled
        #pragma unroll
        for (int ki = 0; ki < 32; ki++) {
            float2 av = *reinterpret_cast<float2*>(&As[ki * 18 + 2 * ty]);
            float2 bv = *reinterpret_cast<float2*>(&Bs[ki * 34 + 2 * tx]);
            a00 += av.x * bv.x; a01 += av.x * bv.y;
            a10 += av.y * bv.x; a11 += av.y * bv.y;
        }
    }
    asm volatile("bar.sync %0, 128;" :: "r"(bar_id));       // compute done

    const int c = c0 + 2 * ty, o = o0 + 2 * tx;
    __half2 h0 = __floats2half2_rn(a00, a01);
    __half2 h1 = __floats2half2_rn(a10, a11);
    *reinterpret_cast<__half2*>(&g_tbl_h[tbl * 65536 + c * 256 + o])       = h0;
    *reinterpret_cast<__half2*>(&g_tbl_h[tbl * 65536 + (c + 1) * 256 + o]) = h1;
}

// ---------------------------------------------------------------------------
// Pool phase: stage K table slices, lookup+HADD2+HMAX2, fold (max+bias) into
// the cross-phase accumulator.
// ---------------------------------------------------------------------------
template<int K>
__device__ __forceinline__ void run_phase(
    char* sm, const unsigned short* schars,
    const __half* __restrict__ gphase,
    const float* __restrict__ bias,
    __half2 acc[2][4],
    int otile, int n_count, int qtotal,
    int tid, int warp, int n_sub, unsigned lane_off)
{
    __syncthreads();  // previous phase done reading SMEM

    const int total16 = K * 2048;          // 16B chunks
    for (int idx = tid; idx < total16; idx += 1024) {
        int j   = idx >> 11;
        int rem = idx & 2047;
        int c   = rem >> 3;
        int f   = rem & 7;
        uint4 v = __ldcg(reinterpret_cast<const uint4*>(
            gphase + j * 65536 + c * 256 + otile * 64 + f * 8));
        *reinterpret_cast<uint4*>(sm + (j * 256 + c) * 128 + f * 16) = v;
    }
    __syncthreads();

    const float* bp = bias + otile * 64 + (lane_off >> 1);
    __half2 bh[4];
    #pragma unroll
    for (int c = 0; c < 4; c++)
        bh[c] = __floats2half2_rn(bp[2 * c], bp[2 * c + 1]);

    const __half2 NEGINF = __float2half2_rn(-60000.0f);

    #pragma unroll
    for (int it = 0; it < 2; it++) {
        const int q = warp + it * 32;
        if (q < qtotal) {
            const int nl  = q * 4 + n_sub;
            const int nlc = (nl < n_count) ? nl : (n_count - 1);

            const unsigned short* cp = schars + nlc * CHSTRIDE;
            uint4 p0 = *reinterpret_cast<const uint4*>(cp);
            uint4 p1 = *reinterpret_cast<const uint4*>(cp + 8);
            uint2 p2 = *reinterpret_cast<const uint2*>(cp + 16);
            unsigned pk[10] = {p0.x, p0.y, p0.z, p0.w,
                               p1.x, p1.y, p1.z, p1.w, p2.x, p2.y};
            unsigned a[LSEQ];
            #pragma unroll
            for (int p = 0; p < LSEQ; p++)
                a[p] = ((pk[p >> 1] >> (16 * (p & 1))) & 0xFFFFu) + lane_off;

            __half2 m0 = NEGINF, m1 = NEGINF, m2 = NEGINF, m3 = NEGINF;
            #pragma unroll
            for (int t = 0; t <= LSEQ - K; t++) {
                uint4 su = *reinterpret_cast<const uint4*>(sm + a[t]);
                __half2 s0 = *reinterpret_cast<__half2*>(&su.x);
                __half2 s1 = *reinterpret_cast<__half2*>(&su.y);
                __half2 s2 = *reinterpret_cast<__half2*>(&su.z);
                __half2 s3 = *reinterpret_cast<__half2*>(&su.w);
                #pragma unroll
                for (int j = 1; j < K; j++) {
                    uint4 ru = *reinterpret_cast<const uint4*>(
                        sm + (unsigned)(j * TBL_BYTES) + a[t + j]);
                    s0 = __hadd2(s0, *reinterpret_cast<__half2*>(&ru.x));
                    s1 = __hadd2(s1, *reinterpret_cast<__half2*>(&ru.y));
                    s2 = __hadd2(s2, *reinterpret_cast<__half2*>(&ru.z));
                    s3 = __hadd2(s3, *reinterpret_cast<__half2*>(&ru.w));
                }
                m0 = __hmax2(m0, s0);
                m1 = __hmax2(m1, s1);
                m2 = __hmax2(m2, s2);
                m3 = __hmax2(m3, s3);
            }

            acc[it][0] = __hmax2(acc[it][0], __hadd2(m0, bh[0]));
            acc[it][1] = __hmax2(acc[it][1], __hadd2(m1, bh[1]));
            acc[it][2] = __hmax2(acc[it][2], __hadd2(m2, bh[2]));
            acc[it][3] = __hmax2(acc[it][3], __hadd2(m3, bh[3]));
        }
    }
}

// ---------------------------------------------------------------------------
__global__ void __launch_bounds__(1024, 1)
fused_cnn_kernel(const int* __restrict__ x, const int* __restrict__ lens,
                 const float* __restrict__ emb,
                 const float* __restrict__ w3, const float* __restrict__ b3,
                 const float* __restrict__ w4, const float* __restrict__ b4,
                 const float* __restrict__ w5, const float* __restrict__ b5,
                 float* __restrict__ out)
{
    extern __shared__ char sm[];
    const int tid     = threadIdx.x;
    const int group   = blockIdx.x;
    const int otile   = blockIdx.y;
    const int bid     = otile * NGRP + group;     // 0..147
    const int n_start = group * NPC;
    const int n_count = min(NTOT - n_start, NPC);

    unsigned short* schars = reinterpret_cast<unsigned short*>(sm + SMEM_CHARS_OFF);

    // ---- char row-offset staging (char * 128B row stride), padded stride 24.
    for (int i = tid; i < n_count * LSEQ; i += 1024) {
        int n = i / LSEQ, p = i - n * LSEQ;
        schars[n * CHSTRIDE + p] =
            (unsigned short)(x[(n_start + n) * LSEQ + p] << 7);
    }

    // ---- balanced table build: 8 groups x 128 threads; jobs gs and
    //      (1184+gs) when gs < 352 -> every CTA runs 10-11 jobs.
    {
        const int grp   = tid >> 7;               // 0..7
        const int tid_g = tid & 127;
        float* As = reinterpret_cast<float*>(sm + grp * GSCRATCH); // 32x18 f32
        float* Bs = As + 32 * 18;                                  // 32x34 f32
        const int gs = grp * NCTA + bid;          // 0..1183
        build_job(gs, As, Bs, emb, w3, w4, w5, tid_g, 1 + grp);
        if (gs < EXTRA)
            build_job(NSLOTS + gs, As, Bs, emb, w3, w4, w5, tid_g, 1 + grp);
    }

    // ---- grid barrier (sense-reversing via generation counter; replay-safe)
    __threadfence();
    __syncthreads();
    if (tid == 0) {
        unsigned gen = g_gen;
        __threadfence();
        if (atomicAdd(&g_count, 1) == NCTA - 1) {
            atomicExch(&g_count, 0);
            __threadfence();
            g_gen = gen + 1;
        } else {
            while (g_gen == gen) { }
        }
    }
    __syncthreads();

    // ---- pool phases
    const int lane  = tid & 31;
    const int warp  = tid >> 5;
    const int n_sub = lane >> 3;
    const unsigned lane_off = (unsigned)((lane & 7) * 16);
    const int qtotal = (n_count + 3) >> 2;

    __half2 acc[2][4];
    #pragma unroll
    for (int i = 0; i < 2; i++)
        #pragma unroll
        for (int c = 0; c < 4; c++) acc[i][c] = __float2half2_rn(0.0f);

    run_phase<3>(sm, schars, g_tbl_h,             b3, acc, otile, n_count, qtotal, tid, warp, n_sub, lane_off);
    run_phase<4>(sm, schars, g_tbl_h + 3 * 65536, b4, acc, otile, n_count, qtotal, tid, warp, n_sub, lane_off);
    run_phase<5>(sm, schars, g_tbl_h + 7 * 65536, b5, acc, otile, n_count, qtotal, tid, warp, n_sub, lane_off);

    // ---- epilogue: one pure store per (n, 8-output slice); masked -> zeros.
    #pragma unroll
    for (int it = 0; it < 2; it++) {
        const int q  = warp + it * 32;
        const int nl = q * 4 + n_sub;
        if (q < qtotal && nl < n_count) {
            const int n = n_start + nl;
            float4 o0 = make_float4(0.f, 0.f, 0.f, 0.f);
            float4 o1 = o0;
            if (lens[n] != 0) {
                float2 f0 = __half22float2(acc[it][0]);
                float2 f1 = __half22float2(acc[it][1]);
                float2 f2 = __half22float2(acc[it][2]);
                float2 f3 = __half22float2(acc[it][3]);
                o0 = make_float4(f0.x, f0.y, f1.x, f1.y);
                o1 = make_float4(f2.x, f2.y, f3.x, f3.y);
            }
            float4* po = reinterpret_cast<float4*>(
                &out[(size_t)n * 256 + otile * 64 + (lane_off >> 1)]);
            po[0] = o0;
            po[1] = o1;
        }
    }
}

// ---------------------------------------------------------------------------
extern "C" void kernel_launch(void* const* d_in, const int* in_sizes, int n_in,
                              void* d_out, int out_size)
{
    const int*   x    = (const int*)  d_in[0];
    const int*   lens = (const int*)  d_in[1];
    const float* emb  = (const float*)d_in[2];
    const float* w3   = (const float*)d_in[3];
    const float* b3   = (const float*)d_in[4];
    const float* w4   = (const float*)d_in[5];
    const float* b4   = (const float*)d_in[6];
    const float* w5   = (const float*)d_in[7];
    const float* b5   = (const float*)d_in[8];
    float* out = (float*)d_out;

    cudaFuncSetAttribute(fused_cnn_kernel,
                         cudaFuncAttributeMaxDynamicSharedMemorySize, SMEM_TOTAL);
    fused_cnn_kernel<<<dim3(NGRP, OTILES), 1024, SMEM_TOTAL>>>(
        x, lens, emb, w3, b3, w4, b4, w5, b5, out);
}

// round 6
// speedup vs baseline: 1.3507x; 1.3507x over previous
#include <cuda_runtime.h>
#include <cuda_fp16.h>

// ---------------------------------------------------------------------------
// CharEmbeddingCNN: embed + 3x conv1d(k=3,4,5) + maxpool + relu + len-mask.
//
//   C_kj[c, o] = sum_i W_k[o, i, j] * emb[c, i]      (12 tables, 256x256, fp16)
//   y_k[n,o,t] = b_k[o] + sum_j C_kj[x[n,t+j], o]
//   out[n,o]   = mask(n) * relu(max_{k,t} y_k[n,o,t])
//
// R6: two kernels. Build = tensor-core mma.m16n8k16 with split-fp16 (hi+lo,
// 3 passes -> fp32-grade accuracy) on 96 CTAs. Pool = proven R3 kernel.
// ---------------------------------------------------------------------------

#define LSEQ  20
#define NTOT  8192            // 64 * 128
#define NPC   222             // n per CTA (37 groups)
#define NGRP  37
#define OTILES 4              // 4 tiles of 64 outputs
#define TBL_BYTES 32768       // per-table SMEM slice: 256 chars * 64 halves * 2B
#define CHSTRIDE 24           // shorts per n (20 used, padded for uint4)
#define SMEM_CHARS_OFF (5 * TBL_BYTES)
#define SMEM_TOTAL (SMEM_CHARS_OFF + NPC * CHSTRIDE * 2)

__device__ __align__(16) __half g_tbl_h[12 * 256 * 256];

// ---------------------------------------------------------------------------
// Stage 1: tensor-core table build.
// Grid (12, 2, 4): tbl, c-block(128), o-block(64). 256 threads = 8 warps;
// warp w computes rows [16w, 16w+16) x 64 outputs (8 n-tiles of m16n8).
// K chunked by 32; A/B staged in SMEM as hi/lo fp16 (padded stride 40).
// 3 mma passes: hi*hi + hi*lo + lo*hi  (al*bl ~2^-22, dropped).
// ---------------------------------------------------------------------------
#define BSTRIDE 40   // halves per staged row (32 data + 8 pad)

__device__ __forceinline__ void mma_16816(
    float d[4], unsigned a0, unsigned a1, unsigned a2, unsigned a3,
    unsigned b0, unsigned b1)
{
    asm volatile(
        "mma.sync.aligned.m16n8k16.row.col.f32.f16.f16.f32 "
        "{%0,%1,%2,%3}, {%4,%5,%6,%7}, {%8,%9}, {%0,%1,%2,%3};"
        : "+f"(d[0]), "+f"(d[1]), "+f"(d[2]), "+f"(d[3])
        : "r"(a0), "r"(a1), "r"(a2), "r"(a3), "r"(b0), "r"(b1));
}

__device__ __forceinline__ unsigned pack_hi(float x, float y) {
    __half2 h = __halves2half2(__float2half_rn(x), __float2half_rn(y));
    return *reinterpret_cast<unsigned*>(&h);
}
__device__ __forceinline__ unsigned pack_lo(float x, float y) {
    __half hx = __float2half_rn(x), hy = __float2half_rn(y);
    __half2 h = __halves2half2(__float2half_rn(x - __half2float(hx)),
                               __float2half_rn(y - __half2float(hy)));
    return *reinterpret_cast<unsigned*>(&h);
}

__global__ void __launch_bounds__(256)
build_tables_tc(const float* __restrict__ emb,
                const float* __restrict__ w3,
                const float* __restrict__ w4,
                const float* __restrict__ w5)
{
    const int tbl = blockIdx.x;
    const int c0  = blockIdx.y * 128;
    const int o0  = blockIdx.z * 64;

    int k, j; const float* w;
    if (tbl < 3)      { k = 3; j = tbl;     w = w3; }
    else if (tbl < 7) { k = 4; j = tbl - 3; w = w4; }
    else              { k = 5; j = tbl - 7; w = w5; }
    const int wk = 256 * k;

    __shared__ __half Ahi[128 * BSTRIDE], Alo[128 * BSTRIDE];
    __shared__ __half Bhi[ 64 * BSTRIDE], Blo[ 64 * BSTRIDE];

    const int tid  = threadIdx.x;
    const int warp = tid >> 5;
    const int lane = tid & 31;
    const int grp  = lane >> 2;     // 0..7
    const int tig  = lane & 3;      // 0..3
    const int r0   = warp * 16 + grp;

    float d[8][4];
    #pragma unroll
    for (int on = 0; on < 8; on++)
        #pragma unroll
        for (int u = 0; u < 4; u++) d[on][u] = 0.0f;

    for (int chunk = 0; chunk < 8; chunk++) {
        const int i0 = chunk * 32;
        __syncthreads();
        // Stage A: 128 c x 32 i  (2048 float-pairs / 256 threads = 8 iters)
        #pragma unroll
        for (int r = 0; r < 8; r++) {
            int idx = tid + r * 256;           // pair index
            int c   = idx >> 4;                // 16 pairs per row
            int p   = idx & 15;
            float2 e = *reinterpret_cast<const float2*>(
                emb + (c0 + c) * 256 + i0 + 2 * p);
            *reinterpret_cast<unsigned*>(&Ahi[c * BSTRIDE + 2 * p]) = pack_hi(e.x, e.y);
            *reinterpret_cast<unsigned*>(&Alo[c * BSTRIDE + 2 * p]) = pack_lo(e.x, e.y);
        }
        // Stage B: 64 o x 32 i (strided gather over w)
        #pragma unroll
        for (int r = 0; r < 4; r++) {
            int idx = tid + r * 256;
            int o   = idx >> 4;
            int p   = idx & 15;
            const float* wp = w + (o0 + o) * wk + (i0 + 2 * p) * k + j;
            float vx = wp[0], vy = wp[k];
            *reinterpret_cast<unsigned*>(&Bhi[o * BSTRIDE + 2 * p]) = pack_hi(vx, vy);
            *reinterpret_cast<unsigned*>(&Blo[o * BSTRIDE + 2 * p]) = pack_lo(vx, vy);
        }
        __syncthreads();

        #pragma unroll
        for (int kc = 0; kc < 32; kc += 16) {
            // A fragments (hoisted across n-tiles)
            unsigned ah0 = *reinterpret_cast<unsigned*>(&Ahi[ r0      * BSTRIDE + kc     + 2 * tig]);
            unsigned ah1 = *reinterpret_cast<unsigned*>(&Ahi[(r0 + 8) * BSTRIDE + kc     + 2 * tig]);
            unsigned ah2 = *reinterpret_cast<unsigned*>(&Ahi[ r0      * BSTRIDE + kc + 8 + 2 * tig]);
            unsigned ah3 = *reinterpret_cast<unsigned*>(&Ahi[(r0 + 8) * BSTRIDE + kc + 8 + 2 * tig]);
            unsigned al0 = *reinterpret_cast<unsigned*>(&Alo[ r0      * BSTRIDE + kc     + 2 * tig]);
            unsigned al1 = *reinterpret_cast<unsigned*>(&Alo[(r0 + 8) * BSTRIDE + kc     + 2 * tig]);
            unsigned al2 = *reinterpret_cast<unsigned*>(&Alo[ r0      * BSTRIDE + kc + 8 + 2 * tig]);
            unsigned al3 = *reinterpret_cast<unsigned*>(&Alo[(r0 + 8) * BSTRIDE + kc + 8 + 2 * tig]);
            #pragma unroll
            for (int on = 0; on < 8; on++) {
                int ob = (on * 8 + grp) * BSTRIDE;
                unsigned bh0 = *reinterpret_cast<unsigned*>(&Bhi[ob + kc     + 2 * tig]);
                unsigned bh1 = *reinterpret_cast<unsigned*>(&Bhi[ob + kc + 8 + 2 * tig]);
                unsigned bl0 = *reinterpret_cast<unsigned*>(&Blo[ob + kc     + 2 * tig]);
                unsigned bl1 = *reinterpret_cast<unsigned*>(&Blo[ob + kc + 8 + 2 * tig]);
                mma_16816(d[on], ah0, ah1, ah2, ah3, bh0, bh1);
                mma_16816(d[on], ah0, ah1, ah2, ah3, bl0, bl1);
                mma_16816(d[on], al0, al1, al2, al3, bh0, bh1);
            }
        }
    }

    // Epilogue: D[c, o] -> fp16 table. d[on] = {(r0, 2tig), (r0, 2tig+1),
    // (r0+8, 2tig), (r0+8, 2tig+1)} at cols o0 + on*8.
    #pragma unroll
    for (int on = 0; on < 8; on++) {
        int col = o0 + on * 8 + 2 * tig;
        __half2 h01 = __floats2half2_rn(d[on][0], d[on][1]);
        __half2 h23 = __floats2half2_rn(d[on][2], d[on][3]);
        *reinterpret_cast<unsigned*>(
            &g_tbl_h[tbl * 65536 + (c0 + r0) * 256 + col]) =
            *reinterpret_cast<unsigned*>(&h01);
        *reinterpret_cast<unsigned*>(
            &g_tbl_h[tbl * 65536 + (c0 + r0 + 8) * 256 + col]) =
            *reinterpret_cast<unsigned*>(&h23);
    }
}

// ---------------------------------------------------------------------------
// Stage 2: pool kernel — identical to the proven R3 version (44.9 us).
// ---------------------------------------------------------------------------
template<int K>
__device__ __forceinline__ void run_phase(
    char* sm, const unsigned short* schars,
    const __half* __restrict__ gphase,
    const float* __restrict__ bias,
    __half2 acc[2][4],
    int otile, int n_count, int qtotal,
    int tid, int warp, int n_sub, unsigned lane_off)
{
    __syncthreads();  // previous phase done reading SMEM

    const int total16 = K * 2048;          // 16B chunks
    for (int idx = tid; idx < total16; idx += 1024) {
        int j   = idx >> 11;
        int rem = idx & 2047;
        int c   = rem >> 3;
        int f   = rem & 7;
        uint4 v = *reinterpret_cast<const uint4*>(
            gphase + j * 65536 + c * 256 + otile * 64 + f * 8);
        *reinterpret_cast<uint4*>(sm + (j * 256 + c) * 128 + f * 16) = v;
    }
    __syncthreads();

    const float* bp = bias + otile * 64 + (lane_off >> 1);
    __half2 bh[4];
    #pragma unroll
    for (int c = 0; c < 4; c++)
        bh[c] = __floats2half2_rn(bp[2 * c], bp[2 * c + 1]);

    const __half2 NEGINF = __float2half2_rn(-60000.0f);

    #pragma unroll
    for (int it = 0; it < 2; it++) {
        const int q = warp + it * 32;
        if (q < qtotal) {
            const int nl  = q * 4 + n_sub;
            const int nlc = (nl < n_count) ? nl : (n_count - 1);

            const unsigned short* cp = schars + nlc * CHSTRIDE;
            uint4 p0 = *reinterpret_cast<const uint4*>(cp);
            uint4 p1 = *reinterpret_cast<const uint4*>(cp + 8);
            uint2 p2 = *reinterpret_cast<const uint2*>(cp + 16);
            unsigned pk[10] = {p0.x, p0.y, p0.z, p0.w,
                               p1.x, p1.y, p1.z, p1.w, p2.x, p2.y};
            unsigned a[LSEQ];
            #pragma unroll
            for (int p = 0; p < LSEQ; p++)
                a[p] = ((pk[p >> 1] >> (16 * (p & 1))) & 0xFFFFu) + lane_off;

            __half2 m0 = NEGINF, m1 = NEGINF, m2 = NEGINF, m3 = NEGINF;
            #pragma unroll
            for (int t = 0; t <= LSEQ - K; t++) {
                uint4 su = *reinterpret_cast<const uint4*>(sm + a[t]);
                __half2 s0 = *reinterpret_cast<__half2*>(&su.x);
                __half2 s1 = *reinterpret_cast<__half2*>(&su.y);
                __half2 s2 = *reinterpret_cast<__half2*>(&su.z);
                __half2 s3 = *reinterpret_cast<__half2*>(&su.w);
                #pragma unroll
                for (int j = 1; j < K; j++) {
                    uint4 ru = *reinterpret_cast<const uint4*>(
                        sm + (unsigned)(j * TBL_BYTES) + a[t + j]);
                    s0 = __hadd2(s0, *reinterpret_cast<__half2*>(&ru.x));
                    s1 = __hadd2(s1, *reinterpret_cast<__half2*>(&ru.y));
                    s2 = __hadd2(s2, *reinterpret_cast<__half2*>(&ru.z));
                    s3 = __hadd2(s3, *reinterpret_cast<__half2*>(&ru.w));
                }
                m0 = __hmax2(m0, s0);
                m1 = __hmax2(m1, s1);
                m2 = __hmax2(m2, s2);
                m3 = __hmax2(m3, s3);
            }

            acc[it][0] = __hmax2(acc[it][0], __hadd2(m0, bh[0]));
            acc[it][1] = __hmax2(acc[it][1], __hadd2(m1, bh[1]));
            acc[it][2] = __hmax2(acc[it][2], __hadd2(m2, bh[2]));
            acc[it][3] = __hmax2(acc[it][3], __hadd2(m3, bh[3]));
        }
    }
}

__global__ void __launch_bounds__(1024, 1)
cnn_pool_kernel(const int* __restrict__ x, const int* __restrict__ lens,
                const float* __restrict__ b3, const float* __restrict__ b4,
                const float* __restrict__ b5, float* __restrict__ out)
{
    extern __shared__ char sm[];
    const int group   = blockIdx.x;
    const int otile   = blockIdx.y;
    const int n_start = group * NPC;
    const int n_count = min(NTOT - n_start, NPC);

    unsigned short* schars = reinterpret_cast<unsigned short*>(sm + SMEM_CHARS_OFF);
    const int tid = threadIdx.x;

    for (int i = tid; i < n_count * LSEQ; i += 1024) {
        int n = i / LSEQ, p = i - n * LSEQ;
        schars[n * CHSTRIDE + p] =
            (unsigned short)(x[(n_start + n) * LSEQ + p] << 7);
    }

    const int lane  = tid & 31;
    const int warp  = tid >> 5;
    const int n_sub = lane >> 3;
    const unsigned lane_off = (unsigned)((lane & 7) * 16);
    const int qtotal = (n_count + 3) >> 2;

    __half2 acc[2][4];
    #pragma unroll
    for (int i = 0; i < 2; i++)
        #pragma unroll
        for (int c = 0; c < 4; c++) acc[i][c] = __float2half2_rn(0.0f);

    run_phase<3>(sm, schars, g_tbl_h,             b3, acc, otile, n_count, qtotal, tid, warp, n_sub, lane_off);
    run_phase<4>(sm, schars, g_tbl_h + 3 * 65536, b4, acc, otile, n_count, qtotal, tid, warp, n_sub, lane_off);
    run_phase<5>(sm, schars, g_tbl_h + 7 * 65536, b5, acc, otile, n_count, qtotal, tid, warp, n_sub, lane_off);

    #pragma unroll
    for (int it = 0; it < 2; it++) {
        const int q  = warp + it * 32;
        const int nl = q * 4 + n_sub;
        if (q < qtotal && nl < n_count) {
            const int n = n_start + nl;
            float4 o0 = make_float4(0.f, 0.f, 0.f, 0.f);
            float4 o1 = o0;
            if (lens[n] != 0) {
                float2 f0 = __half22float2(acc[it][0]);
                float2 f1 = __half22float2(acc[it][1]);
                float2 f2 = __half22float2(acc[it][2]);
                float2 f3 = __half22float2(acc[it][3]);
                o0 = make_float4(f0.x, f0.y, f1.x, f1.y);
                o1 = make_float4(f2.x, f2.y, f3.x, f3.y);
            }
            float4* po = reinterpret_cast<float4*>(
                &out[(size_t)n * 256 + otile * 64 + (lane_off >> 1)]);
            po[0] = o0;
            po[1] = o1;
        }
    }
}

// ---------------------------------------------------------------------------
extern "C" void kernel_launch(void* const* d_in, const int* in_sizes, int n_in,
                              void* d_out, int out_size)
{
    const int*   x    = (const int*)  d_in[0];
    const int*   lens = (const int*)  d_in[1];
    const float* emb  = (const float*)d_in[2];
    const float* w3   = (const float*)d_in[3];
    const float* b3   = (const float*)d_in[4];
    const float* w4   = (const float*)d_in[5];
    const float* b4   = (const float*)d_in[6];
    const float* w5   = (const float*)d_in[7];
    const float* b5   = (const float*)d_in[8];
    float* out = (float*)d_out;

    build_tables_tc<<<dim3(12, 2, 4), 256>>>(emb, w3, w4, w5);

    cudaFuncSetAttribute(cnn_pool_kernel,
                         cudaFuncAttributeMaxDynamicSharedMemorySize, SMEM_TOTAL);
    cnn_pool_kernel<<<dim3(NGRP, OTILES), 1024, SMEM_TOTAL>>>(
        x, lens, b3, b4, b5, out);
}

// round 7
// speedup vs baseline: 1.4011x; 1.0373x over previous
#include <cuda_runtime.h>
#include <cuda_fp16.h>

// ---------------------------------------------------------------------------
// CharEmbeddingCNN: embed + 3x conv1d(k=3,4,5) + maxpool + relu + len-mask.
//
//   C_kj[c, o] = sum_i W_k[o, i, j] * emb[c, i]      (12 tables, 256x256, fp16)
//   y_k[n,o,t] = b_k[o] + sum_j C_kj[x[n,t+j], o]
//   out[n,o]   = mask(n) * relu(max_{k,t} y_k[n,o,t])
//
// R7: ONE kernel. Tensor-core split-fp16 table build (96 CTAs, 256 threads
// each, ~3us) fused ahead of the pool via a grid barrier (148 CTAs, 1/SM,
// single wave). Pool staging via cp.async with a static slot schedule that
// prefetches next-phase tables during current-phase compute.
// ---------------------------------------------------------------------------

#define LSEQ  20
#define NTOT  8192            // 64 * 128
#define NPC   222             // n per CTA (37 groups)
#define NGRP  37
#define OTILES 4              // 4 tiles of 64 outputs
#define TBL_BYTES 32768       // per-slot SMEM slice: 256 chars * 64 halves * 2B
#define CHSTRIDE 24           // shorts per n (20 used, padded for uint4)
#define SMEM_CHARS_OFF (5 * TBL_BYTES)
#define SMEM_TOTAL (SMEM_CHARS_OFF + NPC * CHSTRIDE * 2)
#define NCTA  148
#define BSTRIDE 40            // halves per staged build row (32 data + 8 pad)

__device__ __align__(16) __half g_tbl_h[12 * 256 * 256];
__device__ unsigned g_count = 0;
__device__ volatile unsigned g_gen = 0;

// ---------------------------------------------------------------------------
// cp.async helpers
// ---------------------------------------------------------------------------
#define CP_ASYNC16(dst, src) \
    asm volatile("cp.async.cg.shared.global [%0], [%1], 16;" :: "r"(dst), "l"(src))
#define CP_COMMIT() asm volatile("cp.async.commit_group;")
#define CP_WAIT0()  asm volatile("cp.async.wait_group 0;" ::: "memory")

// Stage one 32KB table slice (256 rows x 128B) into SMEM slot.
__device__ __forceinline__ void stage_slice(
    unsigned sm_u32, int slot, const __half* __restrict__ src, int tid)
{
    const unsigned dst0 = sm_u32 + slot * TBL_BYTES;
    #pragma unroll
    for (int r = 0; r < 2; r++) {
        int idx = tid + r * 1024;          // 0..2047 16B chunks
        CP_ASYNC16(dst0 + idx * 16, src + (idx >> 3) * 256 + (idx & 7) * 8);
    }
}

// ---------------------------------------------------------------------------
// Tensor-core table build (verified in R6). One job = 128c x 64o x 256k.
// job: tbl = job>>3, c0 = ((job>>2)&1)*128, o0 = (job&3)*64.  96 jobs.
// 256 threads (8 warps) per job; named barrier 1 scopes the syncs.
// Split-fp16: 3 mma passes hi*hi + hi*lo + lo*hi.
// ---------------------------------------------------------------------------
__device__ __forceinline__ void mma_16816(
    float d[4], unsigned a0, unsigned a1, unsigned a2, unsigned a3,
    unsigned b0, unsigned b1)
{
    asm volatile(
        "mma.sync.aligned.m16n8k16.row.col.f32.f16.f16.f32 "
        "{%0,%1,%2,%3}, {%4,%5,%6,%7}, {%8,%9}, {%0,%1,%2,%3};"
        : "+f"(d[0]), "+f"(d[1]), "+f"(d[2]), "+f"(d[3])
        : "r"(a0), "r"(a1), "r"(a2), "r"(a3), "r"(b0), "r"(b1));
}

__device__ __forceinline__ unsigned pack_hi(float x, float y) {
    __half2 h = __halves2half2(__float2half_rn(x), __float2half_rn(y));
    return *reinterpret_cast<unsigned*>(&h);
}
__device__ __forceinline__ unsigned pack_lo(float x, float y) {
    __half hx = __float2half_rn(x), hy = __float2half_rn(y);
    __half2 h = __halves2half2(__float2half_rn(x - __half2float(hx)),
                               __float2half_rn(y - __half2float(hy)));
    return *reinterpret_cast<unsigned*>(&h);
}

__device__ void build_job_tc(
    int job, char* smraw,
    const float* __restrict__ emb,
    const float* __restrict__ w3, const float* __restrict__ w4,
    const float* __restrict__ w5, int tid)
{
    const int tbl = job >> 3;
    const int c0  = ((job >> 2) & 1) * 128;
    const int o0  = (job & 3) * 64;

    int k, j; const float* w;
    if (tbl < 3)      { k = 3; j = tbl;     w = w3; }
    else if (tbl < 7) { k = 4; j = tbl - 3; w = w4; }
    else              { k = 5; j = tbl - 7; w = w5; }
    const int wk = 256 * k;

    __half* Ahi = reinterpret_cast<__half*>(smraw);
    __half* Alo = Ahi + 128 * BSTRIDE;
    __half* Bhi = Alo + 128 * BSTRIDE;
    __half* Blo = Bhi + 64 * BSTRIDE;

    const int warp = tid >> 5;
    const int lane = tid & 31;
    const int grp  = lane >> 2;
    const int tig  = lane & 3;
    const int r0   = warp * 16 + grp;

    float d[8][4];
    #pragma unroll
    for (int on = 0; on < 8; on++)
        #pragma unroll
        for (int u = 0; u < 4; u++) d[on][u] = 0.0f;

    for (int chunk = 0; chunk < 8; chunk++) {
        const int i0 = chunk * 32;
        asm volatile("bar.sync 1, 256;" ::: "memory");
        #pragma unroll
        for (int r = 0; r < 8; r++) {          // A: 128c x 32i
            int idx = tid + r * 256;
            int c   = idx >> 4;
            int p   = idx & 15;
            float2 e = *reinterpret_cast<const float2*>(
                emb + (c0 + c) * 256 + i0 + 2 * p);
            *reinterpret_cast<unsigned*>(&Ahi[c * BSTRIDE + 2 * p]) = pack_hi(e.x, e.y);
            *reinterpret_cast<unsigned*>(&Alo[c * BSTRIDE + 2 * p]) = pack_lo(e.x, e.y);
        }
        #pragma unroll
        for (int r = 0; r < 4; r++) {          // B: 64o x 32i
            int idx = tid + r * 256;
            int o   = idx >> 4;
            int p   = idx & 15;
            const float* wp = w + (o0 + o) * wk + (i0 + 2 * p) * k + j;
            float vx = wp[0], vy = wp[k];
            *reinterpret_cast<unsigned*>(&Bhi[o * BSTRIDE + 2 * p]) = pack_hi(vx, vy);
            *reinterpret_cast<unsigned*>(&Blo[o * BSTRIDE + 2 * p]) = pack_lo(vx, vy);
        }
        asm volatile("bar.sync 1, 256;" ::: "memory");

        #pragma unroll
        for (int kc = 0; kc < 32; kc += 16) {
            unsigned ah0 = *reinterpret_cast<unsigned*>(&Ahi[ r0      * BSTRIDE + kc     + 2 * tig]);
            unsigned ah1 = *reinterpret_cast<unsigned*>(&Ahi[(r0 + 8) * BSTRIDE + kc     + 2 * tig]);
            unsigned ah2 = *reinterpret_cast<unsigned*>(&Ahi[ r0      * BSTRIDE + kc + 8 + 2 * tig]);
            unsigned ah3 = *reinterpret_cast<unsigned*>(&Ahi[(r0 + 8) * BSTRIDE + kc + 8 + 2 * tig]);
            unsigned al0 = *reinterpret_cast<unsigned*>(&Alo[ r0      * BSTRIDE + kc     + 2 * tig]);
            unsigned al1 = *reinterpret_cast<unsigned*>(&Alo[(r0 + 8) * BSTRIDE + kc     + 2 * tig]);
            unsigned al2 = *reinterpret_cast<unsigned*>(&Alo[ r0      * BSTRIDE + kc + 8 + 2 * tig]);
            unsigned al3 = *reinterpret_cast<unsigned*>(&Alo[(r0 + 8) * BSTRIDE + kc + 8 + 2 * tig]);
            #pragma unroll
            for (int on = 0; on < 8; on++) {
                int ob = (on * 8 + grp) * BSTRIDE;
                unsigned bh0 = *reinterpret_cast<unsigned*>(&Bhi[ob + kc     + 2 * tig]);
                unsigned bh1 = *reinterpret_cast<unsigned*>(&Bhi[ob + kc + 8 + 2 * tig]);
                unsigned bl0 = *reinterpret_cast<unsigned*>(&Blo[ob + kc     + 2 * tig]);
                unsigned bl1 = *reinterpret_cast<unsigned*>(&Blo[ob + kc + 8 + 2 * tig]);
                mma_16816(d[on], ah0, ah1, ah2, ah3, bh0, bh1);
                mma_16816(d[on], ah0, ah1, ah2, ah3, bl0, bl1);
                mma_16816(d[on], al0, al1, al2, al3, bh0, bh1);
            }
        }
    }

    #pragma unroll
    for (int on = 0; on < 8; on++) {
        int col = o0 + on * 8 + 2 * tig;
        __half2 h01 = __floats2half2_rn(d[on][0], d[on][1]);
        __half2 h23 = __floats2half2_rn(d[on][2], d[on][3]);
        *reinterpret_cast<unsigned*>(
            &g_tbl_h[tbl * 65536 + (c0 + r0) * 256 + col]) =
            *reinterpret_cast<unsigned*>(&h01);
        *reinterpret_cast<unsigned*>(
            &g_tbl_h[tbl * 65536 + (c0 + r0 + 8) * 256 + col]) =
            *reinterpret_cast<unsigned*>(&h23);
    }
}

// ---------------------------------------------------------------------------
// Pool compute phase (no staging inside). Slot bases are template constants.
// ---------------------------------------------------------------------------
template<int K, int S0, int S1, int S2, int S3, int S4>
__device__ __forceinline__ void compute_phase(
    char* sm, const unsigned short* schars,
    const float* __restrict__ bias,
    __half2 acc[2][4],
    int otile, int n_count, int qtotal,
    int warp, int n_sub, unsigned lane_off)
{
    constexpr unsigned SB[5] = {S0 * TBL_BYTES, S1 * TBL_BYTES, S2 * TBL_BYTES,
                                S3 * TBL_BYTES, S4 * TBL_BYTES};

    const float* bp = bias + otile * 64 + (lane_off >> 1);
    __half2 bh[4];
    #pragma unroll
    for (int c = 0; c < 4; c++)
        bh[c] = __floats2half2_rn(bp[2 * c], bp[2 * c + 1]);

    const __half2 NEGINF = __float2half2_rn(-60000.0f);

    #pragma unroll
    for (int it = 0; it < 2; it++) {
        const int q = warp + it * 32;
        if (q < qtotal) {
            const int nl  = q * 4 + n_sub;
            const int nlc = (nl < n_count) ? nl : (n_count - 1);

            const unsigned short* cp = schars + nlc * CHSTRIDE;
            uint4 p0 = *reinterpret_cast<const uint4*>(cp);
            uint4 p1 = *reinterpret_cast<const uint4*>(cp + 8);
            uint2 p2 = *reinterpret_cast<const uint2*>(cp + 16);
            unsigned pk[10] = {p0.x, p0.y, p0.z, p0.w,
                               p1.x, p1.y, p1.z, p1.w, p2.x, p2.y};
            unsigned a[LSEQ];
            #pragma unroll
            for (int p = 0; p < LSEQ; p++)
                a[p] = ((pk[p >> 1] >> (16 * (p & 1))) & 0xFFFFu) + lane_off;

            __half2 m0 = NEGINF, m1 = NEGINF, m2 = NEGINF, m3 = NEGINF;
            #pragma unroll
            for (int t = 0; t <= LSEQ - K; t++) {
                uint4 su = *reinterpret_cast<const uint4*>(sm + SB[0] + a[t]);
                __half2 s0 = *reinterpret_cast<__half2*>(&su.x);
                __half2 s1 = *reinterpret_cast<__half2*>(&su.y);
                __half2 s2 = *reinterpret_cast<__half2*>(&su.z);
                __half2 s3 = *reinterpret_cast<__half2*>(&su.w);
                #pragma unroll
                for (int j = 1; j < K; j++) {
                    uint4 ru = *reinterpret_cast<const uint4*>(
                        sm + SB[j] + a[t + j]);
                    s0 = __hadd2(s0, *reinterpret_cast<__half2*>(&ru.x));
                    s1 = __hadd2(s1, *reinterpret_cast<__half2*>(&ru.y));
                    s2 = __hadd2(s2, *reinterpret_cast<__half2*>(&ru.z));
                    s3 = __hadd2(s3, *reinterpret_cast<__half2*>(&ru.w));
                }
                m0 = __hmax2(m0, s0);
                m1 = __hmax2(m1, s1);
                m2 = __hmax2(m2, s2);
                m3 = __hmax2(m3, s3);
            }

            acc[it][0] = __hmax2(acc[it][0], __hadd2(m0, bh[0]));
            acc[it][1] = __hmax2(acc[it][1], __hadd2(m1, bh[1]));
            acc[it][2] = __hmax2(acc[it][2], __hadd2(m2, bh[2]));
            acc[it][3] = __hmax2(acc[it][3], __hadd2(m3, bh[3]));
        }
    }
}

// ---------------------------------------------------------------------------
__global__ void __launch_bounds__(1024, 1)
fused_cnn_kernel(const int* __restrict__ x, const int* __restrict__ lens,
                 const float* __restrict__ emb,
                 const float* __restrict__ w3, const float* __restrict__ b3,
                 const float* __restrict__ w4, const float* __restrict__ b4,
                 const float* __restrict__ w5, const float* __restrict__ b5,
                 float* __restrict__ out)
{
    extern __shared__ char sm[];
    const int tid     = threadIdx.x;
    const int group   = blockIdx.x;
    const int otile   = blockIdx.y;
    const int bid     = otile * NGRP + group;     // 0..147
    const int n_start = group * NPC;
    const int n_count = min(NTOT - n_start, NPC);

    unsigned short* schars = reinterpret_cast<unsigned short*>(sm + SMEM_CHARS_OFF);

    // ---- parallel prologue: warps 0-7 build (CTAs 0..95); threads 256+
    //      stage char row offsets (char * 128B row stride).
    if (tid >= 256) {
        for (int i = tid - 256; i < n_count * LSEQ; i += 768) {
            int n = i / LSEQ, p = i - n * LSEQ;
            schars[n * CHSTRIDE + p] =
                (unsigned short)(x[(n_start + n) * LSEQ + p] << 7);
        }
    } else if (bid < 96) {
        build_job_tc(bid, sm, emb, w3, w4, w5, tid);
    }

    // ---- grid barrier (sense-reversing via generation counter; replay-safe)
    __threadfence();
    __syncthreads();
    if (tid == 0) {
        unsigned gen = g_gen;
        __threadfence();
        if (atomicAdd(&g_count, 1) == NCTA - 1) {
            atomicExch(&g_count, 0);
            __threadfence();
            g_gen = gen + 1;
        } else {
            while (g_gen == gen) { }
        }
    }
    __syncthreads();

    // ---- pool: static slot schedule with cp.async prefetch.
    //      phase3 slots {0,1,2}; phase4 {3,4,0,1}; phase5 {2,3,4,0,1}.
    const unsigned sm_u32 = (unsigned)__cvta_generic_to_shared(sm);
    const __half* T = g_tbl_h + otile * 64;

    const int lane  = tid & 31;
    const int warp  = tid >> 5;
    const int n_sub = lane >> 3;
    const unsigned lane_off = (unsigned)((lane & 7) * 16);
    const int qtotal = (n_count + 3) >> 2;

    __half2 acc[2][4];
    #pragma unroll
    for (int i = 0; i < 2; i++)
        #pragma unroll
        for (int c = 0; c < 4; c++) acc[i][c] = __float2half2_rn(0.0f);

    // boundary 1: stage k3 (slots 0-2)
    stage_slice(sm_u32, 0, T + 0 * 65536, tid);
    stage_slice(sm_u32, 1, T + 1 * 65536, tid);
    stage_slice(sm_u32, 2, T + 2 * 65536, tid);
    CP_COMMIT(); CP_WAIT0(); __syncthreads();
    // prefetch k4 j0,j1 -> slots 3,4 (unused by phase 3)
    stage_slice(sm_u32, 3, T + 3 * 65536, tid);
    stage_slice(sm_u32, 4, T + 4 * 65536, tid);
    CP_COMMIT();

    compute_phase<3, 0, 1, 2, 0, 0>(sm, schars, b3, acc, otile, n_count,
                                    qtotal, warp, n_sub, lane_off);

    // boundary 2: stage k4 j2,j3 -> slots 0,1 (k3 done)
    __syncthreads();
    stage_slice(sm_u32, 0, T + 5 * 65536, tid);
    stage_slice(sm_u32, 1, T + 6 * 65536, tid);
    CP_COMMIT(); CP_WAIT0(); __syncthreads();
    // prefetch k5 j0 -> slot 2 (unused by phase 4)
    stage_slice(sm_u32, 2, T + 7 * 65536, tid);
    CP_COMMIT();

    compute_phase<4, 3, 4, 0, 1, 0>(sm, schars, b4, acc, otile, n_count,
                                    qtotal, warp, n_sub, lane_off);

    // boundary 3: stage k5 j1..j4 -> slots 3,4,0,1 (k4 done)
    __syncthreads();
    stage_slice(sm_u32, 3, T +  8 * 65536, tid);
    stage_slice(sm_u32, 4, T +  9 * 65536, tid);
    stage_slice(sm_u32, 0, T + 10 * 65536, tid);
    stage_slice(sm_u32, 1, T + 11 * 65536, tid);
    CP_COMMIT(); CP_WAIT0(); __syncthreads();

    compute_phase<5, 2, 3, 4, 0, 1>(sm, schars, b5, acc, otile, n_count,
                                    qtotal, warp, n_sub, lane_off);

    // ---- epilogue: one pure store per (n, 8-output slice); masked -> zeros.
    #pragma unroll
    for (int it = 0; it < 2; it++) {
        const int q  = warp + it * 32;
        const int nl = q * 4 + n_sub;
        if (q < qtotal && nl < n_count) {
            const int n = n_start + nl;
            float4 o0 = make_float4(0.f, 0.f, 0.f, 0.f);
            float4 o1 = o0;
            if (lens[n] != 0) {
                float2 f0 = __half22float2(acc[it][0]);
                float2 f1 = __half22float2(acc[it][1]);
                float2 f2 = __half22float2(acc[it][2]);
                float2 f3 = __half22float2(acc[it][3]);
                o0 = make_float4(f0.x, f0.y, f1.x, f1.y);
                o1 = make_float4(f2.x, f2.y, f3.x, f3.y);
            }
            float4* po = reinterpret_cast<float4*>(
                &out[(size_t)n * 256 + otile * 64 + (lane_off >> 1)]);
            po[0] = o0;
            po[1] = o1;
        }
    }
}

// ---------------------------------------------------------------------------
extern "C" void kernel_launch(void* const* d_in, const int* in_sizes, int n_in,
                              void* d_out, int out_size)
{
    const int*   x    = (const int*)  d_in[0];
    const int*   lens = (const int*)  d_in[1];
    const float* emb  = (const float*)d_in[2];
    const float* w3   = (const float*)d_in[3];
    const float* b3   = (const float*)d_in[4];
    const float* w4   = (const float*)d_in[5];
    const float* b4   = (const float*)d_in[6];
    const float* w5   = (const float*)d_in[7];
    const float* b5   = (const float*)d_in[8];
    float* out = (float*)d_out;

    cudaFuncSetAttribute(fused_cnn_kernel,
                         cudaFuncAttributeMaxDynamicSharedMemorySize, SMEM_TOTAL);
    fused_cnn_kernel<<<dim3(NGRP, OTILES), 1024, SMEM_TOTAL>>>(
        x, lens, emb, w3, b3, w4, b4, w5, b5, out);
}